// round 1
// baseline (speedup 1.0000x reference)
#include <cuda_runtime.h>
#include <cstdint>

// ---------------- problem constants ----------------
#define NIMG 2048          // T*B
#define TSTEPS 64
#define BBATCH 32
#define HID 128

// ---------------- device scratch -------------------
__device__ float g_c1[NIMG * 400 * 32];    // conv1 out [n][20*20][32]
__device__ float g_c2[NIMG * 81 * 64];     // conv2 out [n][9*9][64]
__device__ float g_c3[NIMG * 3136];        // conv3 out [n][49*64]  (= flatten)
__device__ float g_feat[NIMG * 512];       // fc out
__device__ float g_xw[NIMG * 512];         // precomputed x@Wih^T + biases + one-hot
__device__ float g_hT[2][HID * BBATCH];    // double-buffered h, transposed [j][b]
__device__ float g_hs[NIMG * HID];         // all h_t outputs [t*B+b][128]
__device__ unsigned g_bar;

__global__ void init_kernel() {
    if (threadIdx.x == 0) g_bar = 0u;
}

// ---------------- conv1: 84x84x3 -> 20x20x32, k=8 s=4 ----------------
__global__ void __launch_bounds__(256) conv1_kernel(
    const float* __restrict__ img, const float* __restrict__ W,
    const float* __restrict__ bias)
{
    extern __shared__ float sm[];
    float* s_img = sm;           // 21168
    float* s_w   = sm + 21168;   // 6144
    int n = blockIdx.x;
    const float* gi = img + (size_t)n * 21168;
    for (int i = threadIdx.x; i < 21168; i += 256) s_img[i] = gi[i];
    for (int i = threadIdx.x; i < 6144;  i += 256) s_w[i] = W[i];
    __syncthreads();

    int p0 = threadIdx.x;
    int p1 = threadIdx.x + 256;
    bool has1 = (p1 < 400);
    int y0 = p0 / 20, x0 = p0 % 20;
    int y1 = has1 ? p1 / 20 : 0;
    int x1 = has1 ? p1 % 20 : 0;

    float acc0[32], acc1[32];
#pragma unroll
    for (int o = 0; o < 32; o++) { acc0[o] = 0.f; acc1[o] = 0.f; }

    for (int ky = 0; ky < 8; ky++)
        for (int kx = 0; kx < 8; kx++) {
            int b0 = ((y0 * 4 + ky) * 84 + x0 * 4 + kx) * 3;
            int b1 = ((y1 * 4 + ky) * 84 + x1 * 4 + kx) * 3;
#pragma unroll
            for (int ci = 0; ci < 3; ci++) {
                float v0 = s_img[b0 + ci];
                float v1 = s_img[b1 + ci];
                const float* wp = &s_w[((ky * 8 + kx) * 3 + ci) * 32];
#pragma unroll
                for (int o = 0; o < 32; o++) {
                    float wv = wp[o];
                    acc0[o] += v0 * wv;
                    acc1[o] += v1 * wv;
                }
            }
        }
    float* o0 = g_c1 + ((size_t)n * 400 + p0) * 32;
#pragma unroll
    for (int o = 0; o < 32; o++) o0[o] = fmaxf(acc0[o] + __ldg(&bias[o]), 0.f);
    if (has1) {
        float* o1 = g_c1 + ((size_t)n * 400 + p1) * 32;
#pragma unroll
        for (int o = 0; o < 32; o++) o1[o] = fmaxf(acc1[o] + __ldg(&bias[o]), 0.f);
    }
}

// ---------------- conv2: 20x20x32 -> 9x9x64, k=4 s=2 ----------------
// s_in padded: each position chunk 33 floats (bank-conflict-free).
// threads 384: pos = t>>2 (0..95, active<81), ocg = t&3 handles oc = 4*j+ocg.
__global__ void __launch_bounds__(384) conv2_kernel(
    const float* __restrict__ W, const float* __restrict__ bias)
{
    extern __shared__ float sm[];
    float* s_in = sm;            // 400*33 = 13200
    float* s_w  = sm + 13200;    // 32768
    int n = blockIdx.x;
    const float* gi = g_c1 + (size_t)n * 12800;
    for (int i = threadIdx.x; i < 12800; i += 384)
        s_in[(i >> 5) * 33 + (i & 31)] = gi[i];
    for (int i = threadIdx.x; i < 32768; i += 384) s_w[i] = W[i];
    __syncthreads();

    int pos = threadIdx.x >> 2, ocg = threadIdx.x & 3;
    if (pos < 81) {
        int y = pos / 9, x = pos % 9;
        float acc[16];
#pragma unroll
        for (int j = 0; j < 16; j++) acc[j] = 0.f;
        for (int ky = 0; ky < 4; ky++)
            for (int kx = 0; kx < 4; kx++) {
                const float* ip  = &s_in[((y * 2 + ky) * 20 + x * 2 + kx) * 33];
                const float* wp0 = &s_w[((ky * 4 + kx) * 32) * 64];
                for (int ci = 0; ci < 32; ci++) {
                    float v = ip[ci];
                    const float* wp = wp0 + ci * 64 + ocg;
#pragma unroll
                    for (int j = 0; j < 16; j++) acc[j] += v * wp[4 * j];
                }
            }
        float* op = g_c2 + ((size_t)n * 81 + pos) * 64;
#pragma unroll
        for (int j = 0; j < 16; j++)
            op[4 * j + ocg] = fmaxf(acc[j] + __ldg(&bias[4 * j + ocg]), 0.f);
    }
}

// ---------------- conv3: 9x9x64 -> 7x7x64, k=3 s=1 ----------------
__global__ void __launch_bounds__(224) conv3_kernel(
    const float* __restrict__ W, const float* __restrict__ bias)
{
    extern __shared__ float sm[];
    float* s_in = sm;            // 81*65 = 5265
    float* s_w  = sm + 5265;     // 36864
    int n = blockIdx.x;
    const float* gi = g_c2 + (size_t)n * 5184;
    for (int i = threadIdx.x; i < 5184; i += 224)
        s_in[(i >> 6) * 65 + (i & 63)] = gi[i];
    for (int i = threadIdx.x; i < 36864; i += 224) s_w[i] = W[i];
    __syncthreads();

    int pos = threadIdx.x >> 2, ocg = threadIdx.x & 3;
    if (pos < 49) {
        int y = pos / 7, x = pos % 7;
        float acc[16];
#pragma unroll
        for (int j = 0; j < 16; j++) acc[j] = 0.f;
        for (int ky = 0; ky < 3; ky++)
            for (int kx = 0; kx < 3; kx++) {
                const float* ip  = &s_in[((y + ky) * 9 + x + kx) * 65];
                const float* wp0 = &s_w[((ky * 3 + kx) * 64) * 64];
                for (int ci = 0; ci < 64; ci++) {
                    float v = ip[ci];
                    const float* wp = wp0 + ci * 64 + ocg;
#pragma unroll
                    for (int j = 0; j < 16; j++) acc[j] += v * wp[4 * j];
                }
            }
        float* op = g_c3 + (size_t)n * 3136 + pos * 64;
#pragma unroll
        for (int j = 0; j < 16; j++)
            op[4 * j + ocg] = fmaxf(acc[j] + __ldg(&bias[4 * j + ocg]), 0.f);
    }
}

// ---------------- tiled SGEMM 64x64x16, 256 threads, 4x4 microtile ----------
// EPI 0: relu(x + bias1[n])          (FC)
// EPI 1: x + bias1 + bias2 + one-hot gathers from Wih  (xW, B transposed)
template <int EPI, int BTRANS>
__device__ __forceinline__ void sgemm_body(
    const float* __restrict__ A, const float* __restrict__ B,
    float* __restrict__ C, int N, int K, int ldb,
    const float* __restrict__ bias1, const float* __restrict__ bias2,
    const float* __restrict__ WihFull, const int* __restrict__ pos)
{
    __shared__ float As[16][68];
    __shared__ float Bs[16][68];
    int bm = blockIdx.y * 64, bn = blockIdx.x * 64;
    int t = threadIdx.x;
    int tm = t >> 4, tn = t & 15;
    float acc[4][4];
#pragma unroll
    for (int i = 0; i < 4; i++)
#pragma unroll
        for (int j = 0; j < 4; j++) acc[i][j] = 0.f;

    int ar = t >> 2, ac = (t & 3) * 4;
    int brn = t >> 4, bcn = (t & 15) * 4;

    for (int k0 = 0; k0 < K; k0 += 16) {
        float4 av = *(const float4*)(A + (size_t)(bm + ar) * K + k0 + ac);
        As[ac + 0][ar] = av.x; As[ac + 1][ar] = av.y;
        As[ac + 2][ar] = av.z; As[ac + 3][ar] = av.w;
        if (BTRANS == 0) {
            float4 bv = *(const float4*)(B + (size_t)(k0 + brn) * ldb + bn + bcn);
            *(float4*)&Bs[brn][bcn] = bv;
        } else {
            float4 bv = *(const float4*)(B + (size_t)(bn + ar) * ldb + k0 + ac);
            Bs[ac + 0][ar] = bv.x; Bs[ac + 1][ar] = bv.y;
            Bs[ac + 2][ar] = bv.z; Bs[ac + 3][ar] = bv.w;
        }
        __syncthreads();
#pragma unroll
        for (int kk = 0; kk < 16; kk++) {
            float a[4], b4[4];
            *(float4*)a  = *(const float4*)&As[kk][tm * 4];
            *(float4*)b4 = *(const float4*)&Bs[kk][tn * 4];
#pragma unroll
            for (int i = 0; i < 4; i++)
#pragma unroll
                for (int j = 0; j < 4; j++) acc[i][j] += a[i] * b4[j];
        }
        __syncthreads();
    }
#pragma unroll
    for (int i = 0; i < 4; i++) {
        int row = bm + tm * 4 + i;
        int p0 = 0, p1 = 0;
        if (EPI == 1) { p0 = pos[2 * row]; p1 = pos[2 * row + 1]; }
#pragma unroll
        for (int j = 0; j < 4; j++) {
            int col = bn + tn * 4 + j;
            float v = acc[i][j];
            if (EPI == 0) {
                v = fmaxf(v + bias1[col], 0.f);
            } else {
                v += bias1[col] + bias2[col]
                   + WihFull[(size_t)col * 532 + 512 + p0]
                   + WihFull[(size_t)col * 532 + 522 + p1];
            }
            C[(size_t)row * N + col] = v;
        }
    }
}

__global__ void __launch_bounds__(256) fc_kernel(
    const float* __restrict__ Wfc, const float* __restrict__ bfc)
{
    sgemm_body<0, 0>(g_c3, Wfc, g_feat, 512, 3136, 512, bfc, nullptr, nullptr, nullptr);
}

__global__ void __launch_bounds__(256) xw_kernel(
    const float* __restrict__ Wih, const float* __restrict__ bih,
    const float* __restrict__ bhh, const int* __restrict__ pos)
{
    sgemm_body<1, 1>(g_feat, Wih, g_xw, 512, 512, 532, bih, bhh, Wih, pos);
}

// ---------------- persistent LSTM: 32 blocks x 128 threads --------------
__device__ __forceinline__ float sigmoidf_(float x) {
    return 1.0f / (1.0f + __expf(-x));
}

__global__ void __launch_bounds__(128) lstm_kernel(
    const int* __restrict__ done, const float* __restrict__ h0,
    const float* __restrict__ c0, const float* __restrict__ Whh,
    float* __restrict__ out)
{
    int k = blockIdx.x;          // owns hidden units 4k..4k+3
    int t = threadIdx.x;
    int lane = t & 31, w = t >> 5;   // w = gate index in matvec phase

    __shared__ float whh_s[16][HID];     // 16 gate-rows of Whh for this block
    __shared__ float h_sh[HID][BBATCH];  // transposed h
    __shared__ float c_s[4][BBATCH];
    __shared__ float gate_s[4][4][BBATCH]; // [gate][unit][b]
    __shared__ float m_s[BBATCH];

    // load Whh slice: local row r = g*4+ul -> global row g*128 + 4k+ul
    for (int idx = t; idx < 16 * HID; idx += 128) {
        int r = idx >> 7, j = idx & 127;
        int G = (r >> 2) * HID + k * 4 + (r & 3);
        whh_s[r][j] = Whh[(size_t)G * HID + j];
    }
    c_s[w][lane] = c0[lane * HID + k * 4 + w];
    __stcg(&g_hT[0][(k * 4 + w) * BBATCH + lane], h0[lane * HID + k * 4 + w]);
    __threadfence();
    __syncthreads();
    unsigned target = 32;
    if (t == 0) {
        atomicAdd(&g_bar, 1u);
        while (*((volatile unsigned*)&g_bar) < target) {}
    }
    __syncthreads();

    float h_last = 0.f;
    for (int step = 0; step < TSTEPS; step++) {
        int p = step & 1;
        if (t < 32) m_s[t] = 1.0f - (float)done[step * BBATCH + t];
        __syncthreads();
        for (int idx = t; idx < HID * BBATCH; idx += 128) {
            h_sh[idx >> 5][idx & 31] = __ldcg(&g_hT[p][idx]) * m_s[idx & 31];
        }
        __syncthreads();

        // gates: thread (gate=w, batch=lane) accumulates 4 units
        float acc[4];
        const float* xwr = g_xw + (size_t)(step * BBATCH + lane) * 512 + w * HID + k * 4;
#pragma unroll
        for (int ul = 0; ul < 4; ul++) acc[ul] = xwr[ul];
#pragma unroll 4
        for (int j = 0; j < HID; j++) {
            float hv = h_sh[j][lane];
#pragma unroll
            for (int ul = 0; ul < 4; ul++) acc[ul] += hv * whh_s[w * 4 + ul][j];
        }
#pragma unroll
        for (int ul = 0; ul < 4; ul++) gate_s[w][ul][lane] = acc[ul];
        __syncthreads();

        // update: thread (unit=w, batch=lane)
        float iv = sigmoidf_(gate_s[0][w][lane]);
        float fv = sigmoidf_(gate_s[1][w][lane]);
        float gv = tanhf(gate_s[2][w][lane]);
        float ov = sigmoidf_(gate_s[3][w][lane]);
        float cc = fv * (c_s[w][lane] * m_s[lane]) + iv * gv;
        c_s[w][lane] = cc;
        float hh = ov * tanhf(cc);
        h_last = hh;
        __stcg(&g_hT[1 - p][(k * 4 + w) * BBATCH + lane], hh);
        g_hs[(size_t)(step * BBATCH + lane) * HID + k * 4 + w] = hh;
        __threadfence();
        __syncthreads();
        target += 32;
        if (t == 0) {
            atomicAdd(&g_bar, 1u);
            while (*((volatile unsigned*)&g_bar) < target) {}
        }
        __syncthreads();
    }
    // final h, c -> out (B,1,128) regions
    out[12288 + lane * HID + k * 4 + w] = h_last;
    out[16384 + lane * HID + k * 4 + w] = c_s[w][lane];
}

// ---------------- heads: logits (2048x5) + value (2048x1) ---------------
__global__ void heads_kernel(
    const float* __restrict__ Wp, const float* __restrict__ bp,
    const float* __restrict__ Wv, const float* __restrict__ bv,
    float* __restrict__ out)
{
    int row = blockIdx.x * 8 + threadIdx.y;
    int lane = threadIdx.x;
    const float* h = g_hs + (size_t)row * HID;
    float4 hv = *(const float4*)&h[lane * 4];
    float vals[4] = {hv.x, hv.y, hv.z, hv.w};
    float r[6];
#pragma unroll
    for (int a = 0; a < 5; a++) {
        float s = 0.f;
#pragma unroll
        for (int q = 0; q < 4; q++) s += vals[q] * __ldg(&Wp[(lane * 4 + q) * 5 + a]);
        r[a] = s;
    }
    {
        float s = 0.f;
#pragma unroll
        for (int q = 0; q < 4; q++) s += vals[q] * __ldg(&Wv[lane * 4 + q]);
        r[5] = s;
    }
#pragma unroll
    for (int a = 0; a < 6; a++)
#pragma unroll
        for (int off = 16; off > 0; off >>= 1)
            r[a] += __shfl_xor_sync(0xffffffffu, r[a], off);
    if (lane == 0) {
#pragma unroll
        for (int a = 0; a < 5; a++) out[(size_t)row * 5 + a] = r[a] + __ldg(&bp[a]);
        out[10240 + row] = r[5] + __ldg(&bv[0]);
    }
}

// ---------------- launch ----------------
extern "C" void kernel_launch(void* const* d_in, const int* in_sizes, int n_in,
                              void* d_out, int out_size)
{
    const float* image    = (const float*)d_in[0];
    const int*   position = (const int*)d_in[1];
    const int*   done     = (const int*)d_in[2];
    const float* h0       = (const float*)d_in[3];
    const float* c0       = (const float*)d_in[4];
    const float* W1  = (const float*)d_in[5];
    const float* b1  = (const float*)d_in[6];
    const float* W2  = (const float*)d_in[7];
    const float* b2  = (const float*)d_in[8];
    const float* W3  = (const float*)d_in[9];
    const float* b3  = (const float*)d_in[10];
    const float* Wfc = (const float*)d_in[11];
    const float* bfc = (const float*)d_in[12];
    const float* Wih = (const float*)d_in[13];
    const float* Whh = (const float*)d_in[14];
    const float* bih = (const float*)d_in[15];
    const float* bhh = (const float*)d_in[16];
    const float* Wp  = (const float*)d_in[17];
    const float* bp  = (const float*)d_in[18];
    const float* Wv  = (const float*)d_in[19];
    const float* bv  = (const float*)d_in[20];
    float* out = (float*)d_out;

    const int SMEM1 = (21168 + 6144) * 4;           // 109248
    const int SMEM2 = (13200 + 32768) * 4;          // 183872
    const int SMEM3 = (5265 + 36864) * 4;           // 168516
    cudaFuncSetAttribute(conv1_kernel, cudaFuncAttributeMaxDynamicSharedMemorySize, SMEM1);
    cudaFuncSetAttribute(conv2_kernel, cudaFuncAttributeMaxDynamicSharedMemorySize, SMEM2);
    cudaFuncSetAttribute(conv3_kernel, cudaFuncAttributeMaxDynamicSharedMemorySize, SMEM3);

    init_kernel<<<1, 32>>>();
    conv1_kernel<<<NIMG, 256, SMEM1>>>(image, W1, b1);
    conv2_kernel<<<NIMG, 384, SMEM2>>>(W2, b2);
    conv3_kernel<<<NIMG, 224, SMEM3>>>(W3, b3);
    fc_kernel<<<dim3(8, 32), 256>>>(Wfc, bfc);
    xw_kernel<<<dim3(8, 32), 256>>>(Wih, bih, bhh, position);
    lstm_kernel<<<32, 128>>>(done, h0, c0, Whh, out);
    heads_kernel<<<256, dim3(32, 8)>>>(Wp, bp, Wv, bv, out);
}

// round 6
// speedup vs baseline: 1.8800x; 1.8800x over previous
#include <cuda_runtime.h>
#include <cstdint>

// ---------------- problem constants ----------------
#define NIMG 2048          // T*B
#define TSTEPS 64
#define BBATCH 32
#define HID 128

// ---------------- device scratch -------------------
__device__ float g_c1[NIMG * 400 * 32];    // conv1 out [n][20*20][32]
__device__ float g_c2[NIMG * 81 * 64];     // conv2 out [n][9*9][64]
__device__ float g_c3[NIMG * 3136];        // conv3 out [n][49*64]  (= flatten)
__device__ float g_feat[NIMG * 512];       // fc out
__device__ float g_xw[NIMG * 512];         // precomputed x@Wih^T + biases + one-hot
__device__ float g_hT[2][HID * BBATCH];    // double-buffered h, transposed [j][b]
__device__ float g_hs[NIMG * HID];         // all h_t outputs [t*B+b][128]
__device__ unsigned g_bar;

__global__ void init_kernel() {
    if (threadIdx.x == 0) g_bar = 0u;
}

// ---------------- conv1: 84x84x3 -> 20x20x32, k=8 s=4 ----------------
// Proven round-1 kernel; only change: weight reads via float4 LDS (8 LDS.128
// instead of 32 scalar LDS per (ky,kx,ci)). Indices identical.
__global__ void __launch_bounds__(256) conv1_kernel(
    const float* __restrict__ img, const float* __restrict__ W,
    const float* __restrict__ bias)
{
    extern __shared__ float sm[];
    float* s_img = sm;           // 21168
    float* s_w   = sm + 21168;   // 6144  (21168*4 bytes = 16B-aligned offset)
    int n = blockIdx.x;
    const float* gi = img + (size_t)n * 21168;
    for (int i = threadIdx.x; i < 21168; i += 256) s_img[i] = gi[i];
    for (int i = threadIdx.x; i < 6144;  i += 256) s_w[i] = W[i];
    __syncthreads();

    int p0 = threadIdx.x;
    int p1 = threadIdx.x + 256;
    bool has1 = (p1 < 400);
    int y0 = p0 / 20, x0 = p0 % 20;
    int y1 = has1 ? p1 / 20 : 0;
    int x1 = has1 ? p1 % 20 : 0;

    float acc0[32], acc1[32];
#pragma unroll
    for (int o = 0; o < 32; o++) { acc0[o] = 0.f; acc1[o] = 0.f; }

    for (int ky = 0; ky < 8; ky++)
        for (int kx = 0; kx < 8; kx++) {
            int b0 = ((y0 * 4 + ky) * 84 + x0 * 4 + kx) * 3;
            int b1 = ((y1 * 4 + ky) * 84 + x1 * 4 + kx) * 3;
#pragma unroll
            for (int ci = 0; ci < 3; ci++) {
                float v0 = s_img[b0 + ci];
                float v1 = s_img[b1 + ci];
                const float* wp = &s_w[((ky * 8 + kx) * 3 + ci) * 32];
#pragma unroll
                for (int o4 = 0; o4 < 8; o4++) {
                    float4 w4 = *(const float4*)&wp[o4 * 4];
                    acc0[o4 * 4 + 0] += v0 * w4.x;
                    acc0[o4 * 4 + 1] += v0 * w4.y;
                    acc0[o4 * 4 + 2] += v0 * w4.z;
                    acc0[o4 * 4 + 3] += v0 * w4.w;
                    acc1[o4 * 4 + 0] += v1 * w4.x;
                    acc1[o4 * 4 + 1] += v1 * w4.y;
                    acc1[o4 * 4 + 2] += v1 * w4.z;
                    acc1[o4 * 4 + 3] += v1 * w4.w;
                }
            }
        }
    float* o0 = g_c1 + ((size_t)n * 400 + p0) * 32;
#pragma unroll
    for (int o = 0; o < 32; o++) o0[o] = fmaxf(acc0[o] + __ldg(&bias[o]), 0.f);
    if (has1) {
        float* o1 = g_c1 + ((size_t)n * 400 + p1) * 32;
#pragma unroll
        for (int o = 0; o < 32; o++) o1[o] = fmaxf(acc1[o] + __ldg(&bias[o]), 0.f);
    }
}

// ============ conv as SGEMM on the PROVEN 64x64x16 skeleton ============
// C[M x 64] = im2col(A)[M x K] * W[K x 64], M = NIMG*P, OC = 64.
// __device__ body: in/out pointers are bound INSIDE device code by the
// __global__ wrappers below (host code must never reference __device__ globals).
template<int P, int PW, int S, int IW, int CI, int K, int KW>
__device__ __forceinline__ void convsgemm64_body(
    const float* __restrict__ in, const float* __restrict__ Wt,
    const float* __restrict__ bias, float* __restrict__ out)
{
    __shared__ float As[16][68];
    __shared__ float Bs[16][68];
    __shared__ int   s_koff[K];

    const int bm = blockIdx.x * 64;
    const int t  = threadIdx.x;
    const int tm = t >> 4, tn = t & 15;

    for (int i = t; i < K; i += 256) {
        int ky = i / (KW * CI);
        int r  = i - ky * (KW * CI);
        int kx = r / CI;
        int ci = r - kx * CI;
        s_koff[i] = (ky * IW + kx) * CI + ci;
    }

    // A staging role: this thread stages row (bm+ar), k-cols ac..ac+3
    const int ar = t >> 2, ac = (t & 3) * 4;
    int m  = bm + ar;
    int n  = m / P;
    int p  = m - n * P;
    int py = p / PW;
    int px = p - py * PW;
    const float* arow = in + (size_t)n * (IW * IW * CI)
                           + (size_t)(py * S * IW + px * S) * CI;

    const int brn = t >> 4, bcn = (t & 15) * 4;
    __syncthreads();   // s_koff ready

    float acc[4][4];
#pragma unroll
    for (int i = 0; i < 4; i++)
#pragma unroll
        for (int j = 0; j < 4; j++) acc[i][j] = 0.f;

    for (int k0 = 0; k0 < K; k0 += 16) {
        // ---- A tile: im2col gather ----
        As[ac + 0][ar] = __ldg(arow + s_koff[k0 + ac + 0]);
        As[ac + 1][ar] = __ldg(arow + s_koff[k0 + ac + 1]);
        As[ac + 2][ar] = __ldg(arow + s_koff[k0 + ac + 2]);
        As[ac + 3][ar] = __ldg(arow + s_koff[k0 + ac + 3]);
        // ---- B tile: coalesced float4 staging ----
        float4 bv = *(const float4*)(Wt + (size_t)(k0 + brn) * 64 + bcn);
        *(float4*)&Bs[brn][bcn] = bv;
        __syncthreads();
#pragma unroll
        for (int kk = 0; kk < 16; kk++) {
            float a[4], b4[4];
            *(float4*)a  = *(const float4*)&As[kk][tm * 4];
            *(float4*)b4 = *(const float4*)&Bs[kk][tn * 4];
#pragma unroll
            for (int i = 0; i < 4; i++)
#pragma unroll
                for (int j = 0; j < 4; j++) acc[i][j] += a[i] * b4[j];
        }
        __syncthreads();
    }
#pragma unroll
    for (int i = 0; i < 4; i++) {
        int row = bm + tm * 4 + i;
#pragma unroll
        for (int j = 0; j < 4; j++) {
            int col = tn * 4 + j;
            out[(size_t)row * 64 + col] = fmaxf(acc[i][j] + __ldg(&bias[col]), 0.f);
        }
    }
}

// conv2: 20x20x32 -> 9x9x64, k=4 s=2.  M=165888, K=512
__global__ void __launch_bounds__(256) conv2g_kernel(
    const float* __restrict__ W, const float* __restrict__ bias)
{
    convsgemm64_body<81, 9, 2, 20, 32, 512, 4>(g_c1, W, bias, g_c2);
}

// conv3: 9x9x64 -> 7x7x64, k=3 s=1.    M=100352, K=576
__global__ void __launch_bounds__(256) conv3g_kernel(
    const float* __restrict__ W, const float* __restrict__ bias)
{
    convsgemm64_body<49, 7, 1, 9, 64, 576, 3>(g_c2, W, bias, g_c3);
}

// ---------------- tiled SGEMM 64x64x16, 256 threads, 4x4 microtile ----------
// EPI 0: relu(x + bias1[n])          (FC)
// EPI 1: x + bias1 + bias2 + one-hot gathers from Wih  (xW, B transposed)
template <int EPI, int BTRANS>
__device__ __forceinline__ void sgemm_body(
    const float* __restrict__ A, const float* __restrict__ B,
    float* __restrict__ C, int N, int K, int ldb,
    const float* __restrict__ bias1, const float* __restrict__ bias2,
    const float* __restrict__ WihFull, const int* __restrict__ pos)
{
    __shared__ float As[16][68];
    __shared__ float Bs[16][68];
    int bm = blockIdx.y * 64, bn = blockIdx.x * 64;
    int t = threadIdx.x;
    int tm = t >> 4, tn = t & 15;
    float acc[4][4];
#pragma unroll
    for (int i = 0; i < 4; i++)
#pragma unroll
        for (int j = 0; j < 4; j++) acc[i][j] = 0.f;

    int ar = t >> 2, ac = (t & 3) * 4;
    int brn = t >> 4, bcn = (t & 15) * 4;

    for (int k0 = 0; k0 < K; k0 += 16) {
        float4 av = *(const float4*)(A + (size_t)(bm + ar) * K + k0 + ac);
        As[ac + 0][ar] = av.x; As[ac + 1][ar] = av.y;
        As[ac + 2][ar] = av.z; As[ac + 3][ar] = av.w;
        if (BTRANS == 0) {
            float4 bv = *(const float4*)(B + (size_t)(k0 + brn) * ldb + bn + bcn);
            *(float4*)&Bs[brn][bcn] = bv;
        } else {
            float4 bv = *(const float4*)(B + (size_t)(bn + ar) * ldb + k0 + ac);
            Bs[ac + 0][ar] = bv.x; Bs[ac + 1][ar] = bv.y;
            Bs[ac + 2][ar] = bv.z; Bs[ac + 3][ar] = bv.w;
        }
        __syncthreads();
#pragma unroll
        for (int kk = 0; kk < 16; kk++) {
            float a[4], b4[4];
            *(float4*)a  = *(const float4*)&As[kk][tm * 4];
            *(float4*)b4 = *(const float4*)&Bs[kk][tn * 4];
#pragma unroll
            for (int i = 0; i < 4; i++)
#pragma unroll
                for (int j = 0; j < 4; j++) acc[i][j] += a[i] * b4[j];
        }
        __syncthreads();
    }
#pragma unroll
    for (int i = 0; i < 4; i++) {
        int row = bm + tm * 4 + i;
        int p0 = 0, p1 = 0;
        if (EPI == 1) { p0 = pos[2 * row]; p1 = pos[2 * row + 1]; }
#pragma unroll
        for (int j = 0; j < 4; j++) {
            int col = bn + tn * 4 + j;
            float v = acc[i][j];
            if (EPI == 0) {
                v = fmaxf(v + bias1[col], 0.f);
            } else {
                v += bias1[col] + bias2[col]
                   + WihFull[(size_t)col * 532 + 512 + p0]
                   + WihFull[(size_t)col * 532 + 522 + p1];
            }
            C[(size_t)row * N + col] = v;
        }
    }
}

__global__ void __launch_bounds__(256) fc_kernel(
    const float* __restrict__ Wfc, const float* __restrict__ bfc)
{
    sgemm_body<0, 0>(g_c3, Wfc, g_feat, 512, 3136, 512, bfc, nullptr, nullptr, nullptr);
}

__global__ void __launch_bounds__(256) xw_kernel(
    const float* __restrict__ Wih, const float* __restrict__ bih,
    const float* __restrict__ bhh, const int* __restrict__ pos)
{
    sgemm_body<1, 1>(g_feat, Wih, g_xw, 512, 512, 532, bih, bhh, Wih, pos);
}

// ---------------- persistent LSTM: 32 blocks x 128 threads --------------
__device__ __forceinline__ float sigmoidf_(float x) {
    return 1.0f / (1.0f + __expf(-x));
}

__global__ void __launch_bounds__(128) lstm_kernel(
    const int* __restrict__ done, const float* __restrict__ h0,
    const float* __restrict__ c0, const float* __restrict__ Whh,
    float* __restrict__ out)
{
    int k = blockIdx.x;          // owns hidden units 4k..4k+3
    int t = threadIdx.x;
    int lane = t & 31, w = t >> 5;   // w = gate index in matvec phase

    __shared__ float whh_s[16][HID];     // 16 gate-rows of Whh for this block
    __shared__ float h_sh[HID][BBATCH];  // transposed h
    __shared__ float c_s[4][BBATCH];
    __shared__ float gate_s[4][4][BBATCH]; // [gate][unit][b]
    __shared__ float m_s[BBATCH];

    // load Whh slice: local row r = g*4+ul -> global row g*128 + 4k+ul
    for (int idx = t; idx < 16 * HID; idx += 128) {
        int r = idx >> 7, j = idx & 127;
        int G = (r >> 2) * HID + k * 4 + (r & 3);
        whh_s[r][j] = Whh[(size_t)G * HID + j];
    }
    c_s[w][lane] = c0[lane * HID + k * 4 + w];
    __stcg(&g_hT[0][(k * 4 + w) * BBATCH + lane], h0[lane * HID + k * 4 + w]);
    __threadfence();
    __syncthreads();
    unsigned target = 32;
    if (t == 0) {
        atomicAdd(&g_bar, 1u);
        while (*((volatile unsigned*)&g_bar) < target) {}
    }
    __syncthreads();

    float h_last = 0.f;
    for (int step = 0; step < TSTEPS; step++) {
        int p = step & 1;
        if (t < 32) m_s[t] = 1.0f - (float)done[step * BBATCH + t];
        __syncthreads();
        for (int idx = t; idx < HID * BBATCH; idx += 128) {
            h_sh[idx >> 5][idx & 31] = __ldcg(&g_hT[p][idx]) * m_s[idx & 31];
        }
        __syncthreads();

        // gates: thread (gate=w, batch=lane) accumulates 4 units
        float acc[4];
        const float* xwr = g_xw + (size_t)(step * BBATCH + lane) * 512 + w * HID + k * 4;
#pragma unroll
        for (int ul = 0; ul < 4; ul++) acc[ul] = xwr[ul];
#pragma unroll 4
        for (int j = 0; j < HID; j++) {
            float hv = h_sh[j][lane];
#pragma unroll
            for (int ul = 0; ul < 4; ul++) acc[ul] += hv * whh_s[w * 4 + ul][j];
        }
#pragma unroll
        for (int ul = 0; ul < 4; ul++) gate_s[w][ul][lane] = acc[ul];
        __syncthreads();

        // update: thread (unit=w, batch=lane)
        float iv = sigmoidf_(gate_s[0][w][lane]);
        float fv = sigmoidf_(gate_s[1][w][lane]);
        float gv = tanhf(gate_s[2][w][lane]);
        float ov = sigmoidf_(gate_s[3][w][lane]);
        float cc = fv * (c_s[w][lane] * m_s[lane]) + iv * gv;
        c_s[w][lane] = cc;
        float hh = ov * tanhf(cc);
        h_last = hh;
        __stcg(&g_hT[1 - p][(k * 4 + w) * BBATCH + lane], hh);
        g_hs[(size_t)(step * BBATCH + lane) * HID + k * 4 + w] = hh;
        __threadfence();
        __syncthreads();
        target += 32;
        if (t == 0) {
            atomicAdd(&g_bar, 1u);
            while (*((volatile unsigned*)&g_bar) < target) {}
        }
        __syncthreads();
    }
    // final h, c -> out (B,1,128) regions
    out[12288 + lane * HID + k * 4 + w] = h_last;
    out[16384 + lane * HID + k * 4 + w] = c_s[w][lane];
}

// ---------------- heads: logits (2048x5) + value (2048x1) ---------------
__global__ void heads_kernel(
    const float* __restrict__ Wp, const float* __restrict__ bp,
    const float* __restrict__ Wv, const float* __restrict__ bv,
    float* __restrict__ out)
{
    int row = blockIdx.x * 8 + threadIdx.y;
    int lane = threadIdx.x;
    const float* h = g_hs + (size_t)row * HID;
    float4 hv = *(const float4*)&h[lane * 4];
    float vals[4] = {hv.x, hv.y, hv.z, hv.w};
    float r[6];
#pragma unroll
    for (int a = 0; a < 5; a++) {
        float s = 0.f;
#pragma unroll
        for (int q = 0; q < 4; q++) s += vals[q] * __ldg(&Wp[(lane * 4 + q) * 5 + a]);
        r[a] = s;
    }
    {
        float s = 0.f;
#pragma unroll
        for (int q = 0; q < 4; q++) s += vals[q] * __ldg(&Wv[lane * 4 + q]);
        r[5] = s;
    }
#pragma unroll
    for (int a = 0; a < 6; a++)
#pragma unroll
        for (int off = 16; off > 0; off >>= 1)
            r[a] += __shfl_xor_sync(0xffffffffu, r[a], off);
    if (lane == 0) {
#pragma unroll
        for (int a = 0; a < 5; a++) out[(size_t)row * 5 + a] = r[a] + __ldg(&bp[a]);
        out[10240 + row] = r[5] + __ldg(&bv[0]);
    }
}

// ---------------- launch ----------------
extern "C" void kernel_launch(void* const* d_in, const int* in_sizes, int n_in,
                              void* d_out, int out_size)
{
    const float* image    = (const float*)d_in[0];
    const int*   position = (const int*)d_in[1];
    const int*   done     = (const int*)d_in[2];
    const float* h0       = (const float*)d_in[3];
    const float* c0       = (const float*)d_in[4];
    const float* W1  = (const float*)d_in[5];
    const float* b1  = (const float*)d_in[6];
    const float* W2  = (const float*)d_in[7];
    const float* b2  = (const float*)d_in[8];
    const float* W3  = (const float*)d_in[9];
    const float* b3  = (const float*)d_in[10];
    const float* Wfc = (const float*)d_in[11];
    const float* bfc = (const float*)d_in[12];
    const float* Wih = (const float*)d_in[13];
    const float* Whh = (const float*)d_in[14];
    const float* bih = (const float*)d_in[15];
    const float* bhh = (const float*)d_in[16];
    const float* Wp  = (const float*)d_in[17];
    const float* bp  = (const float*)d_in[18];
    const float* Wv  = (const float*)d_in[19];
    const float* bv  = (const float*)d_in[20];
    float* out = (float*)d_out;

    const int SMEM1 = (21168 + 6144) * 4;           // 109248
    cudaFuncSetAttribute(conv1_kernel, cudaFuncAttributeMaxDynamicSharedMemorySize, SMEM1);

    init_kernel<<<1, 32>>>();
    conv1_kernel<<<NIMG, 256, SMEM1>>>(image, W1, b1);
    conv2g_kernel<<<165888 / 64, 256>>>(W2, b2);
    conv3g_kernel<<<100352 / 64, 256>>>(W3, b3);
    fc_kernel<<<dim3(8, 32), 256>>>(Wfc, bfc);
    xw_kernel<<<dim3(8, 32), 256>>>(Wih, bih, bhh, position);
    lstm_kernel<<<32, 128>>>(done, h0, c0, Whh, out);
    heads_kernel<<<256, dim3(32, 8)>>>(Wp, bp, Wv, bv, out);
}

// round 8
// speedup vs baseline: 2.3346x; 1.2418x over previous
#include <cuda_runtime.h>
#include <cstdint>

// ---------------- problem constants ----------------
#define NIMG 2048          // T*B
#define TSTEPS 64
#define BBATCH 32
#define HID 128

// ---------------- device scratch -------------------
__device__ float g_c1[NIMG * 400 * 32];    // conv1 out [n][20*20][32]
__device__ float g_c2[NIMG * 81 * 64];     // conv2 out [n][9*9][64]
__device__ float g_c3[NIMG * 3136];        // conv3 out [n][49*64]  (= flatten)
__device__ float g_feat[NIMG * 512];       // fc out
__device__ float g_xw[NIMG * 512];         // precomputed x@Wih^T + biases + one-hot
__device__ float g_hT[2][HID * BBATCH];    // double-buffered h, transposed [j][b]
__device__ float g_hs[NIMG * HID];         // all h_t outputs [t*B+b][128]
__device__ unsigned g_bar;

__global__ void init_kernel() {
    if (threadIdx.x == 0) g_bar = 0u;
}

// ================= implicit-GEMM conv (device body) =================
// out[m, oc] = relu( sum_k in[rowoff(m) + koff(k)] * W[k, oc] + bias[oc] )
//   m = n*P + py*PW + px ;  k = (ky*KW + kx)*CI + ci
// Tiles: BM x OC, BK=16, 256 threads, 8x4 microtile.
// NOTE: all __device__ global buffers are bound INSIDE the __global__
// wrappers below — host code must never reference them.
template<int P, int PW, int S, int IW, int CI, int OC, int K, int KW, int BM>
__device__ __forceinline__ void convgemm_body(
    const float* __restrict__ in, const float* __restrict__ Wt,
    const float* __restrict__ bias, float* __restrict__ out)
{
    constexpr int IMGSZ = IW * IW * CI;
    constexpr int AS  = (BM == 128) ? 136 : 260;   // smem stride (16B-aligned)
    constexpr int BSS = OC + 4;
    constexpr int TN  = OC / 4;                    // threads along N
    constexpr int LA  = BM / 16;                   // A rows per thread / k-iter

    __shared__ int   s_koff[K];
    __shared__ float As[16][AS];
    __shared__ float Bs[16][BSS];

    const int t  = threadIdx.x;
    const int m0 = blockIdx.x * BM;

    for (int i = t; i < K; i += 256) {
        int ky = i / (KW * CI);
        int r  = i - ky * (KW * CI);
        int kx = r / CI;
        int ci = r - kx * CI;
        s_koff[i] = (ky * IW + kx) * CI + ci;
    }

    // per-thread A-row base offsets (rows r = (t>>4) + 16*l)
    int rowoff[LA];
#pragma unroll
    for (int l = 0; l < LA; l++) {
        int m  = m0 + (t >> 4) + 16 * l;
        int n  = m / P;
        int p  = m - n * P;
        int py = p / PW;
        int px = p - py * PW;
        rowoff[l] = n * IMGSZ + (py * S * IW + px * S) * CI;
    }
    __syncthreads();

    const int tm  = t / TN;
    const int tn  = t - tm * TN;
    const int kkA = t & 15;
    const int mrA = t >> 4;

    float acc[8][4];
#pragma unroll
    for (int i = 0; i < 8; i++)
#pragma unroll
        for (int j = 0; j < 4; j++) acc[i][j] = 0.f;

    for (int k0 = 0; k0 < K; k0 += 16) {
        // ---- stage A tile (im2col gather) ----
        int kof = s_koff[k0 + kkA];
#pragma unroll
        for (int l = 0; l < LA; l++)
            As[kkA][mrA + 16 * l] = __ldg(&in[(size_t)rowoff[l] + kof]);

        // ---- stage B tile (weights, coalesced float4) ----
        if (OC == 64) {
            int brn = t >> 4, bcn = (t & 15) * 4;
            float4 bv = *(const float4*)&Wt[(size_t)(k0 + brn) * OC + bcn];
            *(float4*)&Bs[brn][bcn] = bv;
        } else {                 // OC == 32
            if (t < 128) {
                int brn = t >> 3, bcn = (t & 7) * 4;
                float4 bv = *(const float4*)&Wt[(size_t)(k0 + brn) * OC + bcn];
                *(float4*)&Bs[brn][bcn] = bv;
            }
        }
        __syncthreads();

#pragma unroll
        for (int kk = 0; kk < 16; kk++) {
            float a[8], b[4];
            *(float4*)&a[0] = *(const float4*)&As[kk][tm * 8];
            *(float4*)&a[4] = *(const float4*)&As[kk][tm * 8 + 4];
            *(float4*)&b[0] = *(const float4*)&Bs[kk][tn * 4];
#pragma unroll
            for (int i = 0; i < 8; i++)
#pragma unroll
                for (int j = 0; j < 4; j++)
                    acc[i][j] = fmaf(a[i], b[j], acc[i][j]);
        }
        __syncthreads();
    }

    float4 bv = *(const float4*)&bias[tn * 4];
    float bb[4] = {bv.x, bv.y, bv.z, bv.w};
#pragma unroll
    for (int i = 0; i < 8; i++) {
        int m = m0 + tm * 8 + i;
        float4 o;
        o.x = fmaxf(acc[i][0] + bb[0], 0.f);
        o.y = fmaxf(acc[i][1] + bb[1], 0.f);
        o.z = fmaxf(acc[i][2] + bb[2], 0.f);
        o.w = fmaxf(acc[i][3] + bb[3], 0.f);
        *(float4*)&out[(size_t)m * OC + tn * 4] = o;
    }
}

// conv1: 84x84x3 -> 20x20x32, k=8 s=4.  M=819200, K=192, OC=32, BM=256
__global__ void __launch_bounds__(256) conv1g_kernel(
    const float* __restrict__ img, const float* __restrict__ W,
    const float* __restrict__ bias)
{
    convgemm_body<400, 20, 4, 84, 3, 32, 192, 8, 256>(img, W, bias, g_c1);
}

// conv2: 20x20x32 -> 9x9x64, k=4 s=2.   M=165888, K=512, OC=64, BM=128
__global__ void __launch_bounds__(256) conv2g_kernel(
    const float* __restrict__ W, const float* __restrict__ bias)
{
    convgemm_body<81, 9, 2, 20, 32, 64, 512, 4, 128>(g_c1, W, bias, g_c2);
}

// conv3: 9x9x64 -> 7x7x64, k=3 s=1.     M=100352, K=576, OC=64, BM=128
__global__ void __launch_bounds__(256) conv3g_kernel(
    const float* __restrict__ W, const float* __restrict__ bias)
{
    convgemm_body<49, 7, 1, 9, 64, 64, 576, 3, 128>(g_c2, W, bias, g_c3);
}

// ---------------- tiled SGEMM 64x64x16, 256 threads, 4x4 microtile ----------
// EPI 0: relu(x + bias1[n])          (FC)
// EPI 1: x + bias1 + bias2 + one-hot gathers from Wih  (xW, B transposed)
template <int EPI, int BTRANS>
__device__ __forceinline__ void sgemm_body(
    const float* __restrict__ A, const float* __restrict__ B,
    float* __restrict__ C, int N, int K, int ldb,
    const float* __restrict__ bias1, const float* __restrict__ bias2,
    const float* __restrict__ WihFull, const int* __restrict__ pos)
{
    __shared__ float As[16][68];
    __shared__ float Bs[16][68];
    int bm = blockIdx.y * 64, bn = blockIdx.x * 64;
    int t = threadIdx.x;
    int tm = t >> 4, tn = t & 15;
    float acc[4][4];
#pragma unroll
    for (int i = 0; i < 4; i++)
#pragma unroll
        for (int j = 0; j < 4; j++) acc[i][j] = 0.f;

    int ar = t >> 2, ac = (t & 3) * 4;
    int brn = t >> 4, bcn = (t & 15) * 4;

    for (int k0 = 0; k0 < K; k0 += 16) {
        float4 av = *(const float4*)(A + (size_t)(bm + ar) * K + k0 + ac);
        As[ac + 0][ar] = av.x; As[ac + 1][ar] = av.y;
        As[ac + 2][ar] = av.z; As[ac + 3][ar] = av.w;
        if (BTRANS == 0) {
            float4 bv = *(const float4*)(B + (size_t)(k0 + brn) * ldb + bn + bcn);
            *(float4*)&Bs[brn][bcn] = bv;
        } else {
            float4 bv = *(const float4*)(B + (size_t)(bn + ar) * ldb + k0 + ac);
            Bs[ac + 0][ar] = bv.x; Bs[ac + 1][ar] = bv.y;
            Bs[ac + 2][ar] = bv.z; Bs[ac + 3][ar] = bv.w;
        }
        __syncthreads();
#pragma unroll
        for (int kk = 0; kk < 16; kk++) {
            float a[4], b4[4];
            *(float4*)a  = *(const float4*)&As[kk][tm * 4];
            *(float4*)b4 = *(const float4*)&Bs[kk][tn * 4];
#pragma unroll
            for (int i = 0; i < 4; i++)
#pragma unroll
                for (int j = 0; j < 4; j++) acc[i][j] += a[i] * b4[j];
        }
        __syncthreads();
    }
#pragma unroll
    for (int i = 0; i < 4; i++) {
        int row = bm + tm * 4 + i;
        int p0 = 0, p1 = 0;
        if (EPI == 1) { p0 = pos[2 * row]; p1 = pos[2 * row + 1]; }
#pragma unroll
        for (int j = 0; j < 4; j++) {
            int col = bn + tn * 4 + j;
            float v = acc[i][j];
            if (EPI == 0) {
                v = fmaxf(v + bias1[col], 0.f);
            } else {
                v += bias1[col] + bias2[col]
                   + WihFull[(size_t)col * 532 + 512 + p0]
                   + WihFull[(size_t)col * 532 + 522 + p1];
            }
            C[(size_t)row * N + col] = v;
        }
    }
}

__global__ void __launch_bounds__(256) fc_kernel(
    const float* __restrict__ Wfc, const float* __restrict__ bfc)
{
    sgemm_body<0, 0>(g_c3, Wfc, g_feat, 512, 3136, 512, bfc, nullptr, nullptr, nullptr);
}

__global__ void __launch_bounds__(256) xw_kernel(
    const float* __restrict__ Wih, const float* __restrict__ bih,
    const float* __restrict__ bhh, const int* __restrict__ pos)
{
    sgemm_body<1, 1>(g_feat, Wih, g_xw, 512, 512, 532, bih, bhh, Wih, pos);
}

// ---------------- persistent LSTM: 32 blocks x 128 threads --------------
__device__ __forceinline__ float sigmoidf_(float x) {
    return 1.0f / (1.0f + __expf(-x));
}

__global__ void __launch_bounds__(128) lstm_kernel(
    const int* __restrict__ done, const float* __restrict__ h0,
    const float* __restrict__ c0, const float* __restrict__ Whh,
    float* __restrict__ out)
{
    int k = blockIdx.x;          // owns hidden units 4k..4k+3
    int t = threadIdx.x;
    int lane = t & 31, w = t >> 5;   // w = gate index in matvec phase

    __shared__ float whh_s[16][HID];     // 16 gate-rows of Whh for this block
    __shared__ float h_sh[HID][BBATCH];  // transposed h
    __shared__ float c_s[4][BBATCH];
    __shared__ float gate_s[4][4][BBATCH]; // [gate][unit][b]
    __shared__ float m_s[BBATCH];

    // load Whh slice: local row r = g*4+ul -> global row g*128 + 4k+ul
    for (int idx = t; idx < 16 * HID; idx += 128) {
        int r = idx >> 7, j = idx & 127;
        int G = (r >> 2) * HID + k * 4 + (r & 3);
        whh_s[r][j] = Whh[(size_t)G * HID + j];
    }
    c_s[w][lane] = c0[lane * HID + k * 4 + w];
    __stcg(&g_hT[0][(k * 4 + w) * BBATCH + lane], h0[lane * HID + k * 4 + w]);
    __threadfence();
    __syncthreads();
    unsigned target = 32;
    if (t == 0) {
        atomicAdd(&g_bar, 1u);
        while (*((volatile unsigned*)&g_bar) < target) {}
    }
    __syncthreads();

    float h_last = 0.f;
    for (int step = 0; step < TSTEPS; step++) {
        int p = step & 1;
        if (t < 32) m_s[t] = 1.0f - (float)done[step * BBATCH + t];
        __syncthreads();
        for (int idx = t; idx < HID * BBATCH; idx += 128) {
            h_sh[idx >> 5][idx & 31] = __ldcg(&g_hT[p][idx]) * m_s[idx & 31];
        }
        __syncthreads();

        // gates: thread (gate=w, batch=lane) accumulates 4 units
        float acc[4];
        const float* xwr = g_xw + (size_t)(step * BBATCH + lane) * 512 + w * HID + k * 4;
#pragma unroll
        for (int ul = 0; ul < 4; ul++) acc[ul] = xwr[ul];
#pragma unroll 4
        for (int j = 0; j < HID; j++) {
            float hv = h_sh[j][lane];
#pragma unroll
            for (int ul = 0; ul < 4; ul++) acc[ul] += hv * whh_s[w * 4 + ul][j];
        }
#pragma unroll
        for (int ul = 0; ul < 4; ul++) gate_s[w][ul][lane] = acc[ul];
        __syncthreads();

        // update: thread (unit=w, batch=lane)
        float iv = sigmoidf_(gate_s[0][w][lane]);
        float fv = sigmoidf_(gate_s[1][w][lane]);
        float gv = tanhf(gate_s[2][w][lane]);
        float ov = sigmoidf_(gate_s[3][w][lane]);
        float cc = fv * (c_s[w][lane] * m_s[lane]) + iv * gv;
        c_s[w][lane] = cc;
        float hh = ov * tanhf(cc);
        h_last = hh;
        __stcg(&g_hT[1 - p][(k * 4 + w) * BBATCH + lane], hh);
        g_hs[(size_t)(step * BBATCH + lane) * HID + k * 4 + w] = hh;
        __threadfence();
        __syncthreads();
        target += 32;
        if (t == 0) {
            atomicAdd(&g_bar, 1u);
            while (*((volatile unsigned*)&g_bar) < target) {}
        }
        __syncthreads();
    }
    // final h, c -> out (B,1,128) regions
    out[12288 + lane * HID + k * 4 + w] = h_last;
    out[16384 + lane * HID + k * 4 + w] = c_s[w][lane];
}

// ---------------- heads: logits (2048x5) + value (2048x1) ---------------
__global__ void heads_kernel(
    const float* __restrict__ Wp, const float* __restrict__ bp,
    const float* __restrict__ Wv, const float* __restrict__ bv,
    float* __restrict__ out)
{
    int row = blockIdx.x * 8 + threadIdx.y;
    int lane = threadIdx.x;
    const float* h = g_hs + (size_t)row * HID;
    float4 hv = *(const float4*)&h[lane * 4];
    float vals[4] = {hv.x, hv.y, hv.z, hv.w};
    float r[6];
#pragma unroll
    for (int a = 0; a < 5; a++) {
        float s = 0.f;
#pragma unroll
        for (int q = 0; q < 4; q++) s += vals[q] * __ldg(&Wp[(lane * 4 + q) * 5 + a]);
        r[a] = s;
    }
    {
        float s = 0.f;
#pragma unroll
        for (int q = 0; q < 4; q++) s += vals[q] * __ldg(&Wv[lane * 4 + q]);
        r[5] = s;
    }
#pragma unroll
    for (int a = 0; a < 6; a++)
#pragma unroll
        for (int off = 16; off > 0; off >>= 1)
            r[a] += __shfl_xor_sync(0xffffffffu, r[a], off);
    if (lane == 0) {
#pragma unroll
        for (int a = 0; a < 5; a++) out[(size_t)row * 5 + a] = r[a] + __ldg(&bp[a]);
        out[10240 + row] = r[5] + __ldg(&bv[0]);
    }
}

// ---------------- launch ----------------
extern "C" void kernel_launch(void* const* d_in, const int* in_sizes, int n_in,
                              void* d_out, int out_size)
{
    const float* image    = (const float*)d_in[0];
    const int*   position = (const int*)d_in[1];
    const int*   done     = (const int*)d_in[2];
    const float* h0       = (const float*)d_in[3];
    const float* c0       = (const float*)d_in[4];
    const float* W1  = (const float*)d_in[5];
    const float* b1  = (const float*)d_in[6];
    const float* W2  = (const float*)d_in[7];
    const float* b2  = (const float*)d_in[8];
    const float* W3  = (const float*)d_in[9];
    const float* b3  = (const float*)d_in[10];
    const float* Wfc = (const float*)d_in[11];
    const float* bfc = (const float*)d_in[12];
    const float* Wih = (const float*)d_in[13];
    const float* Whh = (const float*)d_in[14];
    const float* bih = (const float*)d_in[15];
    const float* bhh = (const float*)d_in[16];
    const float* Wp  = (const float*)d_in[17];
    const float* bp  = (const float*)d_in[18];
    const float* Wv  = (const float*)d_in[19];
    const float* bv  = (const float*)d_in[20];
    float* out = (float*)d_out;

    init_kernel<<<1, 32>>>();
    conv1g_kernel<<<819200 / 256, 256>>>(image, W1, b1);
    conv2g_kernel<<<165888 / 128, 256>>>(W2, b2);
    conv3g_kernel<<<100352 / 128, 256>>>(W3, b3);
    fc_kernel<<<dim3(8, 32), 256>>>(Wfc, bfc);
    xw_kernel<<<dim3(8, 32), 256>>>(Wih, bih, bhh, position);
    lstm_kernel<<<32, 128>>>(done, h0, c0, Whh, out);
    heads_kernel<<<256, dim3(32, 8)>>>(Wp, bp, Wv, bv, out);
}

// round 9
// speedup vs baseline: 2.3779x; 1.0186x over previous
#include <cuda_runtime.h>
#include <cstdint>

// ---------------- problem constants ----------------
#define NIMG 2048          // T*B
#define TSTEPS 64
#define BBATCH 32
#define HID 128

// ---------------- device scratch -------------------
__device__ float g_c1[NIMG * 400 * 32];    // conv1 out [n][20*20][32]
__device__ float g_c2[NIMG * 81 * 64];     // conv2 out [n][9*9][64]
__device__ float g_c3[NIMG * 3136];        // conv3 out [n][49*64]  (= flatten)
__device__ float g_feat[NIMG * 512];       // fc out
__device__ float g_xw[NIMG * 512];         // precomputed x@Wih^T + biases + one-hot
__device__ float g_hT[2][HID * BBATCH];    // double-buffered h, transposed [j][b]
__device__ float g_hs[NIMG * HID];         // all h_t outputs [t*B+b][128]
__device__ unsigned g_bar;

__global__ void init_kernel() {
    if (threadIdx.x == 0) g_bar = 0u;
}

// ---------------- packed f32x2 helpers (sm_103a FFMA2 path) ----------------
__device__ __forceinline__ void fma2(unsigned long long& d,
                                     unsigned long long a,
                                     unsigned long long b) {
    asm("fma.rn.f32x2 %0, %1, %2, %3;" : "=l"(d) : "l"(a), "l"(b), "l"(d));
}
__device__ __forceinline__ unsigned long long pack2(float lo, float hi) {
    unsigned long long r;
    asm("mov.b64 %0, {%1, %2};" : "=l"(r) : "f"(lo), "f"(hi));
    return r;
}
__device__ __forceinline__ float2 unpack2(unsigned long long v) {
    float2 r;
    asm("mov.b64 {%0, %1}, %2;" : "=f"(r.x), "=f"(r.y) : "l"(v));
    return r;
}

// ================= implicit-GEMM conv (device body, f32x2 core) ============
// out[m, oc] = relu( sum_k in[rowoff(m) + koff(k)] * W[k, oc] + bias[oc] )
//   m = n*P + py*PW + px ;  k = (ky*KW + kx)*CI + ci
// Tiles: BM x OC, BK=16, 256 threads, 8x4 microtile (as 4 M-pairs x 4 N).
template<int P, int PW, int S, int IW, int CI, int OC, int K, int KW, int BM>
__device__ __forceinline__ void convgemm_body(
    const float* __restrict__ in, const float* __restrict__ Wt,
    const float* __restrict__ bias, float* __restrict__ out)
{
    constexpr int IMGSZ = IW * IW * CI;
    constexpr int AS  = (BM == 128) ? 136 : 260;   // smem stride (8B/16B-aligned)
    constexpr int BSS = OC + 4;
    constexpr int TN  = OC / 4;                    // threads along N
    constexpr int LA  = BM / 16;                   // A rows per thread / k-iter

    __shared__ int s_koff[K];
    __shared__ __align__(16) float As[16][AS];
    __shared__ __align__(16) float Bs[16][BSS];

    const int t  = threadIdx.x;
    const int m0 = blockIdx.x * BM;

    for (int i = t; i < K; i += 256) {
        int ky = i / (KW * CI);
        int r  = i - ky * (KW * CI);
        int kx = r / CI;
        int ci = r - kx * CI;
        s_koff[i] = (ky * IW + kx) * CI + ci;
    }

    // per-thread A-row base offsets (rows r = (t>>4) + 16*l)
    int rowoff[LA];
#pragma unroll
    for (int l = 0; l < LA; l++) {
        int m  = m0 + (t >> 4) + 16 * l;
        int n  = m / P;
        int p  = m - n * P;
        int py = p / PW;
        int px = p - py * PW;
        rowoff[l] = n * IMGSZ + (py * S * IW + px * S) * CI;
    }
    __syncthreads();

    const int tm  = t / TN;
    const int tn  = t - tm * TN;
    const int kkA = t & 15;
    const int mrA = t >> 4;

    // acc2[i2][j]: M-rows (tm*8+2*i2, tm*8+2*i2+1) x N-col (tn*4+j), packed f32x2
    unsigned long long acc2[4][4];
#pragma unroll
    for (int i = 0; i < 4; i++)
#pragma unroll
        for (int j = 0; j < 4; j++) acc2[i][j] = 0ull;

    for (int k0 = 0; k0 < K; k0 += 16) {
        // ---- stage A tile (im2col gather) ----
        int kof = s_koff[k0 + kkA];
#pragma unroll
        for (int l = 0; l < LA; l++)
            As[kkA][mrA + 16 * l] = __ldg(&in[(size_t)rowoff[l] + kof]);

        // ---- stage B tile (weights, coalesced float4) ----
        if (OC == 64) {
            int brn = t >> 4, bcn = (t & 15) * 4;
            float4 bv = *(const float4*)&Wt[(size_t)(k0 + brn) * OC + bcn];
            *(float4*)&Bs[brn][bcn] = bv;
        } else {                 // OC == 32
            if (t < 128) {
                int brn = t >> 3, bcn = (t & 7) * 4;
                float4 bv = *(const float4*)&Wt[(size_t)(k0 + brn) * OC + bcn];
                *(float4*)&Bs[brn][bcn] = bv;
            }
        }
        __syncthreads();

#pragma unroll
        for (int kk = 0; kk < 16; kk++) {
            const unsigned long long* ap =
                reinterpret_cast<const unsigned long long*>(&As[kk][tm * 8]);
            unsigned long long a2[4] = {ap[0], ap[1], ap[2], ap[3]};
            float4 bq = *(const float4*)&Bs[kk][tn * 4];
            unsigned long long b2[4] = {pack2(bq.x, bq.x), pack2(bq.y, bq.y),
                                        pack2(bq.z, bq.z), pack2(bq.w, bq.w)};
#pragma unroll
            for (int i = 0; i < 4; i++)
#pragma unroll
                for (int j = 0; j < 4; j++)
                    fma2(acc2[i][j], a2[i], b2[j]);
        }
        __syncthreads();
    }

    float4 bv = *(const float4*)&bias[tn * 4];
    float bb[4] = {bv.x, bv.y, bv.z, bv.w};
#pragma unroll
    for (int i2 = 0; i2 < 4; i2++) {
        int mlo = m0 + tm * 8 + 2 * i2;
        float2 u0 = unpack2(acc2[i2][0]);
        float2 u1 = unpack2(acc2[i2][1]);
        float2 u2 = unpack2(acc2[i2][2]);
        float2 u3 = unpack2(acc2[i2][3]);
        float4 olo, ohi;
        olo.x = fmaxf(u0.x + bb[0], 0.f);  ohi.x = fmaxf(u0.y + bb[0], 0.f);
        olo.y = fmaxf(u1.x + bb[1], 0.f);  ohi.y = fmaxf(u1.y + bb[1], 0.f);
        olo.z = fmaxf(u2.x + bb[2], 0.f);  ohi.z = fmaxf(u2.y + bb[2], 0.f);
        olo.w = fmaxf(u3.x + bb[3], 0.f);  ohi.w = fmaxf(u3.y + bb[3], 0.f);
        *(float4*)&out[(size_t)mlo * OC + tn * 4]       = olo;
        *(float4*)&out[(size_t)(mlo + 1) * OC + tn * 4] = ohi;
    }
}

// conv1: 84x84x3 -> 20x20x32, k=8 s=4.  M=819200, K=192, OC=32, BM=256
__global__ void __launch_bounds__(256) conv1g_kernel(
    const float* __restrict__ img, const float* __restrict__ W,
    const float* __restrict__ bias)
{
    convgemm_body<400, 20, 4, 84, 3, 32, 192, 8, 256>(img, W, bias, g_c1);
}

// conv2: 20x20x32 -> 9x9x64, k=4 s=2.   M=165888, K=512, OC=64, BM=128
__global__ void __launch_bounds__(256) conv2g_kernel(
    const float* __restrict__ W, const float* __restrict__ bias)
{
    convgemm_body<81, 9, 2, 20, 32, 64, 512, 4, 128>(g_c1, W, bias, g_c2);
}

// conv3: 9x9x64 -> 7x7x64, k=3 s=1.     M=100352, K=576, OC=64, BM=128
__global__ void __launch_bounds__(256) conv3g_kernel(
    const float* __restrict__ W, const float* __restrict__ bias)
{
    convgemm_body<49, 7, 1, 9, 64, 64, 576, 3, 128>(g_c2, W, bias, g_c3);
}

// ---------------- tiled SGEMM 64x64x16, 256 threads, f32x2 core -------------
// 4x4 microtile as 2 M-pairs x 4 N.
// EPI 0: relu(x + bias1[n])          (FC)
// EPI 1: x + bias1 + bias2 + one-hot gathers from Wih  (xW, B transposed)
template <int EPI, int BTRANS>
__device__ __forceinline__ void sgemm_body(
    const float* __restrict__ A, const float* __restrict__ B,
    float* __restrict__ C, int N, int K, int ldb,
    const float* __restrict__ bias1, const float* __restrict__ bias2,
    const float* __restrict__ WihFull, const int* __restrict__ pos)
{
    __shared__ __align__(16) float As[16][68];
    __shared__ __align__(16) float Bs[16][68];
    int bm = blockIdx.y * 64, bn = blockIdx.x * 64;
    int t = threadIdx.x;
    int tm = t >> 4, tn = t & 15;

    unsigned long long acc2[2][4];
#pragma unroll
    for (int i = 0; i < 2; i++)
#pragma unroll
        for (int j = 0; j < 4; j++) acc2[i][j] = 0ull;

    int ar = t >> 2, ac = (t & 3) * 4;
    int brn = t >> 4, bcn = (t & 15) * 4;

    for (int k0 = 0; k0 < K; k0 += 16) {
        float4 av = *(const float4*)(A + (size_t)(bm + ar) * K + k0 + ac);
        As[ac + 0][ar] = av.x; As[ac + 1][ar] = av.y;
        As[ac + 2][ar] = av.z; As[ac + 3][ar] = av.w;
        if (BTRANS == 0) {
            float4 bv = *(const float4*)(B + (size_t)(k0 + brn) * ldb + bn + bcn);
            *(float4*)&Bs[brn][bcn] = bv;
        } else {
            float4 bv = *(const float4*)(B + (size_t)(bn + ar) * ldb + k0 + ac);
            Bs[ac + 0][ar] = bv.x; Bs[ac + 1][ar] = bv.y;
            Bs[ac + 2][ar] = bv.z; Bs[ac + 3][ar] = bv.w;
        }
        __syncthreads();
#pragma unroll
        for (int kk = 0; kk < 16; kk++) {
            const unsigned long long* ap =
                reinterpret_cast<const unsigned long long*>(&As[kk][tm * 4]);
            unsigned long long a2[2] = {ap[0], ap[1]};
            float4 bq = *(const float4*)&Bs[kk][tn * 4];
            unsigned long long b2[4] = {pack2(bq.x, bq.x), pack2(bq.y, bq.y),
                                        pack2(bq.z, bq.z), pack2(bq.w, bq.w)};
#pragma unroll
            for (int i = 0; i < 2; i++)
#pragma unroll
                for (int j = 0; j < 4; j++)
                    fma2(acc2[i][j], a2[i], b2[j]);
        }
        __syncthreads();
    }
#pragma unroll
    for (int i2 = 0; i2 < 2; i2++) {
        float2 u[4];
#pragma unroll
        for (int j = 0; j < 4; j++) u[j] = unpack2(acc2[i2][j]);
#pragma unroll
        for (int half = 0; half < 2; half++) {
            int row = bm + tm * 4 + 2 * i2 + half;
            int p0 = 0, p1 = 0;
            if (EPI == 1) { p0 = pos[2 * row]; p1 = pos[2 * row + 1]; }
#pragma unroll
            for (int j = 0; j < 4; j++) {
                int col = bn + tn * 4 + j;
                float v = half ? u[j].y : u[j].x;
                if (EPI == 0) {
                    v = fmaxf(v + bias1[col], 0.f);
                } else {
                    v += bias1[col] + bias2[col]
                       + WihFull[(size_t)col * 532 + 512 + p0]
                       + WihFull[(size_t)col * 532 + 522 + p1];
                }
                C[(size_t)row * N + col] = v;
            }
        }
    }
}

__global__ void __launch_bounds__(256) fc_kernel(
    const float* __restrict__ Wfc, const float* __restrict__ bfc)
{
    sgemm_body<0, 0>(g_c3, Wfc, g_feat, 512, 3136, 512, bfc, nullptr, nullptr, nullptr);
}

__global__ void __launch_bounds__(256) xw_kernel(
    const float* __restrict__ Wih, const float* __restrict__ bih,
    const float* __restrict__ bhh, const int* __restrict__ pos)
{
    sgemm_body<1, 1>(g_feat, Wih, g_xw, 512, 512, 532, bih, bhh, Wih, pos);
}

// ---------------- persistent LSTM: 32 blocks x 128 threads --------------
__device__ __forceinline__ float sigmoidf_(float x) {
    return 1.0f / (1.0f + __expf(-x));
}

__global__ void __launch_bounds__(128) lstm_kernel(
    const int* __restrict__ done, const float* __restrict__ h0,
    const float* __restrict__ c0, const float* __restrict__ Whh,
    float* __restrict__ out)
{
    int k = blockIdx.x;          // owns hidden units 4k..4k+3
    int t = threadIdx.x;
    int lane = t & 31, w = t >> 5;   // w = gate index in matvec phase

    __shared__ float whh_s[16][HID];     // 16 gate-rows of Whh for this block
    __shared__ float h_sh[HID][BBATCH];  // transposed h
    __shared__ float c_s[4][BBATCH];
    __shared__ float gate_s[4][4][BBATCH]; // [gate][unit][b]
    __shared__ float m_s[BBATCH];

    // load Whh slice: local row r = g*4+ul -> global row g*128 + 4k+ul
    for (int idx = t; idx < 16 * HID; idx += 128) {
        int r = idx >> 7, j = idx & 127;
        int G = (r >> 2) * HID + k * 4 + (r & 3);
        whh_s[r][j] = Whh[(size_t)G * HID + j];
    }
    c_s[w][lane] = c0[lane * HID + k * 4 + w];
    __stcg(&g_hT[0][(k * 4 + w) * BBATCH + lane], h0[lane * HID + k * 4 + w]);
    __threadfence();
    __syncthreads();
    unsigned target = 32;
    if (t == 0) {
        atomicAdd(&g_bar, 1u);
        while (*((volatile unsigned*)&g_bar) < target) {}
    }
    __syncthreads();

    float h_last = 0.f;
    for (int step = 0; step < TSTEPS; step++) {
        int p = step & 1;
        if (t < 32) m_s[t] = 1.0f - (float)done[step * BBATCH + t];
        __syncthreads();
        for (int idx = t; idx < HID * BBATCH; idx += 128) {
            h_sh[idx >> 5][idx & 31] = __ldcg(&g_hT[p][idx]) * m_s[idx & 31];
        }
        __syncthreads();

        // gates: thread (gate=w, batch=lane) accumulates 4 units
        float acc[4];
        const float* xwr = g_xw + (size_t)(step * BBATCH + lane) * 512 + w * HID + k * 4;
#pragma unroll
        for (int ul = 0; ul < 4; ul++) acc[ul] = xwr[ul];
#pragma unroll 4
        for (int j = 0; j < HID; j++) {
            float hv = h_sh[j][lane];
#pragma unroll
            for (int ul = 0; ul < 4; ul++) acc[ul] += hv * whh_s[w * 4 + ul][j];
        }
#pragma unroll
        for (int ul = 0; ul < 4; ul++) gate_s[w][ul][lane] = acc[ul];
        __syncthreads();

        // update: thread (unit=w, batch=lane)
        float iv = sigmoidf_(gate_s[0][w][lane]);
        float fv = sigmoidf_(gate_s[1][w][lane]);
        float gv = tanhf(gate_s[2][w][lane]);
        float ov = sigmoidf_(gate_s[3][w][lane]);
        float cc = fv * (c_s[w][lane] * m_s[lane]) + iv * gv;
        c_s[w][lane] = cc;
        float hh = ov * tanhf(cc);
        h_last = hh;
        __stcg(&g_hT[1 - p][(k * 4 + w) * BBATCH + lane], hh);
        g_hs[(size_t)(step * BBATCH + lane) * HID + k * 4 + w] = hh;
        __threadfence();
        __syncthreads();
        target += 32;
        if (t == 0) {
            atomicAdd(&g_bar, 1u);
            while (*((volatile unsigned*)&g_bar) < target) {}
        }
        __syncthreads();
    }
    // final h, c -> out (B,1,128) regions
    out[12288 + lane * HID + k * 4 + w] = h_last;
    out[16384 + lane * HID + k * 4 + w] = c_s[w][lane];
}

// ---------------- heads: logits (2048x5) + value (2048x1) ---------------
__global__ void heads_kernel(
    const float* __restrict__ Wp, const float* __restrict__ bp,
    const float* __restrict__ Wv, const float* __restrict__ bv,
    float* __restrict__ out)
{
    int row = blockIdx.x * 8 + threadIdx.y;
    int lane = threadIdx.x;
    const float* h = g_hs + (size_t)row * HID;
    float4 hv = *(const float4*)&h[lane * 4];
    float vals[4] = {hv.x, hv.y, hv.z, hv.w};
    float r[6];
#pragma unroll
    for (int a = 0; a < 5; a++) {
        float s = 0.f;
#pragma unroll
        for (int q = 0; q < 4; q++) s += vals[q] * __ldg(&Wp[(lane * 4 + q) * 5 + a]);
        r[a] = s;
    }
    {
        float s = 0.f;
#pragma unroll
        for (int q = 0; q < 4; q++) s += vals[q] * __ldg(&Wv[lane * 4 + q]);
        r[5] = s;
    }
#pragma unroll
    for (int a = 0; a < 6; a++)
#pragma unroll
        for (int off = 16; off > 0; off >>= 1)
            r[a] += __shfl_xor_sync(0xffffffffu, r[a], off);
    if (lane == 0) {
#pragma unroll
        for (int a = 0; a < 5; a++) out[(size_t)row * 5 + a] = r[a] + __ldg(&bp[a]);
        out[10240 + row] = r[5] + __ldg(&bv[0]);
    }
}

// ---------------- launch ----------------
extern "C" void kernel_launch(void* const* d_in, const int* in_sizes, int n_in,
                              void* d_out, int out_size)
{
    const float* image    = (const float*)d_in[0];
    const int*   position = (const int*)d_in[1];
    const int*   done     = (const int*)d_in[2];
    const float* h0       = (const float*)d_in[3];
    const float* c0       = (const float*)d_in[4];
    const float* W1  = (const float*)d_in[5];
    const float* b1  = (const float*)d_in[6];
    const float* W2  = (const float*)d_in[7];
    const float* b2  = (const float*)d_in[8];
    const float* W3  = (const float*)d_in[9];
    const float* b3  = (const float*)d_in[10];
    const float* Wfc = (const float*)d_in[11];
    const float* bfc = (const float*)d_in[12];
    const float* Wih = (const float*)d_in[13];
    const float* Whh = (const float*)d_in[14];
    const float* bih = (const float*)d_in[15];
    const float* bhh = (const float*)d_in[16];
    const float* Wp  = (const float*)d_in[17];
    const float* bp  = (const float*)d_in[18];
    const float* Wv  = (const float*)d_in[19];
    const float* bv  = (const float*)d_in[20];
    float* out = (float*)d_out;

    init_kernel<<<1, 32>>>();
    conv1g_kernel<<<819200 / 256, 256>>>(image, W1, b1);
    conv2g_kernel<<<165888 / 128, 256>>>(W2, b2);
    conv3g_kernel<<<100352 / 128, 256>>>(W3, b3);
    fc_kernel<<<dim3(8, 32), 256>>>(Wfc, bfc);
    xw_kernel<<<dim3(8, 32), 256>>>(Wih, bih, bhh, position);
    lstm_kernel<<<32, 128>>>(done, h0, c0, Whh, out);
    heads_kernel<<<256, dim3(32, 8)>>>(Wp, bp, Wv, bv, out);
}

// round 10
// speedup vs baseline: 2.4567x; 1.0331x over previous
#include <cuda_runtime.h>
#include <cstdint>

// ---------------- problem constants ----------------
#define NIMG 2048          // T*B
#define TSTEPS 64
#define BBATCH 32
#define HID 128

// ---------------- device scratch -------------------
__device__ float g_c1[NIMG * 400 * 32];    // conv1 out [n][20*20][32]
__device__ float g_c2[NIMG * 81 * 64];     // conv2 out [n][9*9][64]
__device__ float g_c3[NIMG * 3136];        // conv3 out [n][49*64]  (= flatten)
__device__ float g_feat[NIMG * 512];       // fc out
__device__ float g_xw[NIMG * 512];         // precomputed x@Wih^T + biases + one-hot
__device__ float g_hT[2][HID * BBATCH];    // double-buffered h, transposed [j][b]
__device__ float g_hs[NIMG * HID];         // all h_t outputs [t*B+b][128]
__device__ unsigned g_bar;

__global__ void init_kernel() {
    if (threadIdx.x == 0) g_bar = 0u;
}

// ---------------- packed f32x2 helpers (sm_103a FFMA2 path) ----------------
__device__ __forceinline__ void fma2(unsigned long long& d,
                                     unsigned long long a,
                                     unsigned long long b) {
    asm("fma.rn.f32x2 %0, %1, %2, %3;" : "=l"(d) : "l"(a), "l"(b), "l"(d));
}
__device__ __forceinline__ unsigned long long pack2(float lo, float hi) {
    unsigned long long r;
    asm("mov.b64 %0, {%1, %2};" : "=l"(r) : "f"(lo), "f"(hi));
    return r;
}
__device__ __forceinline__ float2 unpack2(unsigned long long v) {
    float2 r;
    asm("mov.b64 {%0, %1}, %2;" : "=f"(r.x), "=f"(r.y) : "l"(v));
    return r;
}

// ================= implicit-GEMM conv (device body, f32x2 + prefetch) ======
// out[m, oc] = relu( sum_k in[rowoff(m) + koff(k)] * W[k, oc] + bias[oc] )
//   m = n*P + py*PW + px ;  k = (ky*KW + kx)*CI + ci
// Tiles: BM x OC, BK=16, 256 threads, 8x4 microtile (as 4 M-pairs x 4 N).
// Register double-buffering: tile i+1 is LDG'd into registers while tile i
// is computed from smem, hiding global-load latency behind the FMA phase.
template<int P, int PW, int S, int IW, int CI, int OC, int K, int KW, int BM>
__device__ __forceinline__ void convgemm_body(
    const float* __restrict__ in, const float* __restrict__ Wt,
    const float* __restrict__ bias, float* __restrict__ out)
{
    constexpr int IMGSZ = IW * IW * CI;
    constexpr int AS  = (BM == 128) ? 136 : 260;   // smem stride (16B-aligned)
    constexpr int BSS = OC + 4;
    constexpr int TN  = OC / 4;                    // threads along N
    constexpr int LA  = BM / 16;                   // A rows per thread / k-iter
    constexpr int NIT = K / 16;

    __shared__ int s_koff[K];
    __shared__ __align__(16) float As[16][AS];
    __shared__ __align__(16) float Bs[16][BSS];

    const int t  = threadIdx.x;
    const int m0 = blockIdx.x * BM;

    for (int i = t; i < K; i += 256) {
        int ky = i / (KW * CI);
        int r  = i - ky * (KW * CI);
        int kx = r / CI;
        int ci = r - kx * CI;
        s_koff[i] = (ky * IW + kx) * CI + ci;
    }

    // per-thread A-row base offsets (rows r = (t>>4) + 16*l)
    int rowoff[LA];
#pragma unroll
    for (int l = 0; l < LA; l++) {
        int m  = m0 + (t >> 4) + 16 * l;
        int n  = m / P;
        int p  = m - n * P;
        int py = p / PW;
        int px = p - py * PW;
        rowoff[l] = n * IMGSZ + (py * S * IW + px * S) * CI;
    }
    __syncthreads();   // s_koff ready

    const int tm  = t / TN;
    const int tn  = t - tm * TN;
    const int kkA = t & 15;
    const int mrA = t >> 4;
    // B staging role
    const int brn = (OC == 64) ? (t >> 4) : (t >> 3);
    const int bcn = (OC == 64) ? ((t & 15) * 4) : ((t & 7) * 4);
    const bool bact = (OC == 64) || (t < 128);

    // prefetch registers
    float  aReg[LA];
    float4 bReg;

    // ---- load tile k0 into registers ----
    auto load_tile = [&](int k0) {
        int kof = s_koff[k0 + kkA];
#pragma unroll
        for (int l = 0; l < LA; l++)
            aReg[l] = __ldg(&in[(size_t)rowoff[l] + kof]);
        if (bact)
            bReg = *(const float4*)&Wt[(size_t)(k0 + brn) * OC + bcn];
    };
    // ---- store registers into smem tiles ----
    auto store_tile = [&]() {
#pragma unroll
        for (int l = 0; l < LA; l++)
            As[kkA][mrA + 16 * l] = aReg[l];
        if (bact)
            *(float4*)&Bs[brn][bcn] = bReg;
    };

    // acc2[i2][j]: M-rows (tm*8+2*i2, tm*8+2*i2+1) x N-col (tn*4+j), packed f32x2
    unsigned long long acc2[4][4];
#pragma unroll
    for (int i = 0; i < 4; i++)
#pragma unroll
        for (int j = 0; j < 4; j++) acc2[i][j] = 0ull;

    load_tile(0);
    store_tile();
    __syncthreads();

    for (int it = 1; it <= NIT; it++) {
        if (it < NIT) load_tile(it * 16);   // prefetch next tile (overlaps compute)

#pragma unroll
        for (int kk = 0; kk < 16; kk++) {
            const unsigned long long* ap =
                reinterpret_cast<const unsigned long long*>(&As[kk][tm * 8]);
            unsigned long long a2[4] = {ap[0], ap[1], ap[2], ap[3]};
            float4 bq = *(const float4*)&Bs[kk][tn * 4];
            unsigned long long b2[4] = {pack2(bq.x, bq.x), pack2(bq.y, bq.y),
                                        pack2(bq.z, bq.z), pack2(bq.w, bq.w)};
#pragma unroll
            for (int i = 0; i < 4; i++)
#pragma unroll
                for (int j = 0; j < 4; j++)
                    fma2(acc2[i][j], a2[i], b2[j]);
        }

        if (it < NIT) {
            __syncthreads();   // everyone done reading current tiles
            store_tile();
            __syncthreads();   // new tiles visible
        }
    }

    float4 bv = *(const float4*)&bias[tn * 4];
    float bb[4] = {bv.x, bv.y, bv.z, bv.w};
#pragma unroll
    for (int i2 = 0; i2 < 4; i2++) {
        int mlo = m0 + tm * 8 + 2 * i2;
        float2 u0 = unpack2(acc2[i2][0]);
        float2 u1 = unpack2(acc2[i2][1]);
        float2 u2 = unpack2(acc2[i2][2]);
        float2 u3 = unpack2(acc2[i2][3]);
        float4 olo, ohi;
        olo.x = fmaxf(u0.x + bb[0], 0.f);  ohi.x = fmaxf(u0.y + bb[0], 0.f);
        olo.y = fmaxf(u1.x + bb[1], 0.f);  ohi.y = fmaxf(u1.y + bb[1], 0.f);
        olo.z = fmaxf(u2.x + bb[2], 0.f);  ohi.z = fmaxf(u2.y + bb[2], 0.f);
        olo.w = fmaxf(u3.x + bb[3], 0.f);  ohi.w = fmaxf(u3.y + bb[3], 0.f);
        *(float4*)&out[(size_t)mlo * OC + tn * 4]       = olo;
        *(float4*)&out[(size_t)(mlo + 1) * OC + tn * 4] = ohi;
    }
}

// conv1: 84x84x3 -> 20x20x32, k=8 s=4.  M=819200, K=192, OC=32, BM=256
__global__ void __launch_bounds__(256) conv1g_kernel(
    const float* __restrict__ img, const float* __restrict__ W,
    const float* __restrict__ bias)
{
    convgemm_body<400, 20, 4, 84, 3, 32, 192, 8, 256>(img, W, bias, g_c1);
}

// conv2: 20x20x32 -> 9x9x64, k=4 s=2.   M=165888, K=512, OC=64, BM=128
__global__ void __launch_bounds__(256) conv2g_kernel(
    const float* __restrict__ W, const float* __restrict__ bias)
{
    convgemm_body<81, 9, 2, 20, 32, 64, 512, 4, 128>(g_c1, W, bias, g_c2);
}

// conv3: 9x9x64 -> 7x7x64, k=3 s=1.     M=100352, K=576, OC=64, BM=128
__global__ void __launch_bounds__(256) conv3g_kernel(
    const float* __restrict__ W, const float* __restrict__ bias)
{
    convgemm_body<49, 7, 1, 9, 64, 64, 576, 3, 128>(g_c2, W, bias, g_c3);
}

// ---------------- tiled SGEMM 64x64x16, f32x2 core + prefetch ---------------
// 4x4 microtile as 2 M-pairs x 4 N.
// EPI 0: relu(x + bias1[n])          (FC)
// EPI 1: x + bias1 + bias2 + one-hot gathers from Wih  (xW, B transposed)
template <int EPI, int BTRANS>
__device__ __forceinline__ void sgemm_body(
    const float* __restrict__ A, const float* __restrict__ B,
    float* __restrict__ C, int N, int K, int ldb,
    const float* __restrict__ bias1, const float* __restrict__ bias2,
    const float* __restrict__ WihFull, const int* __restrict__ pos)
{
    __shared__ __align__(16) float As[16][68];
    __shared__ __align__(16) float Bs[16][68];
    int bm = blockIdx.y * 64, bn = blockIdx.x * 64;
    int t = threadIdx.x;
    int tm = t >> 4, tn = t & 15;

    unsigned long long acc2[2][4];
#pragma unroll
    for (int i = 0; i < 2; i++)
#pragma unroll
        for (int j = 0; j < 4; j++) acc2[i][j] = 0ull;

    int ar = t >> 2, ac = (t & 3) * 4;
    int brn = t >> 4, bcn = (t & 15) * 4;

    float4 avR, bvR;
    auto load_tile = [&](int k0) {
        avR = *(const float4*)(A + (size_t)(bm + ar) * K + k0 + ac);
        if (BTRANS == 0)
            bvR = *(const float4*)(B + (size_t)(k0 + brn) * ldb + bn + bcn);
        else
            bvR = *(const float4*)(B + (size_t)(bn + ar) * ldb + k0 + ac);
    };
    auto store_tile = [&]() {
        As[ac + 0][ar] = avR.x; As[ac + 1][ar] = avR.y;
        As[ac + 2][ar] = avR.z; As[ac + 3][ar] = avR.w;
        if (BTRANS == 0) {
            *(float4*)&Bs[brn][bcn] = bvR;
        } else {
            Bs[ac + 0][ar] = bvR.x; Bs[ac + 1][ar] = bvR.y;
            Bs[ac + 2][ar] = bvR.z; Bs[ac + 3][ar] = bvR.w;
        }
    };

    const int NIT = K / 16;
    load_tile(0);
    store_tile();
    __syncthreads();

    for (int it = 1; it <= NIT; it++) {
        if (it < NIT) load_tile(it * 16);

#pragma unroll
        for (int kk = 0; kk < 16; kk++) {
            const unsigned long long* ap =
                reinterpret_cast<const unsigned long long*>(&As[kk][tm * 4]);
            unsigned long long a2[2] = {ap[0], ap[1]};
            float4 bq = *(const float4*)&Bs[kk][tn * 4];
            unsigned long long b2[4] = {pack2(bq.x, bq.x), pack2(bq.y, bq.y),
                                        pack2(bq.z, bq.z), pack2(bq.w, bq.w)};
#pragma unroll
            for (int i = 0; i < 2; i++)
#pragma unroll
                for (int j = 0; j < 4; j++)
                    fma2(acc2[i][j], a2[i], b2[j]);
        }

        if (it < NIT) {
            __syncthreads();
            store_tile();
            __syncthreads();
        }
    }
#pragma unroll
    for (int i2 = 0; i2 < 2; i2++) {
        float2 u[4];
#pragma unroll
        for (int j = 0; j < 4; j++) u[j] = unpack2(acc2[i2][j]);
#pragma unroll
        for (int half = 0; half < 2; half++) {
            int row = bm + tm * 4 + 2 * i2 + half;
            int p0 = 0, p1 = 0;
            if (EPI == 1) { p0 = pos[2 * row]; p1 = pos[2 * row + 1]; }
#pragma unroll
            for (int j = 0; j < 4; j++) {
                int col = bn + tn * 4 + j;
                float v = half ? u[j].y : u[j].x;
                if (EPI == 0) {
                    v = fmaxf(v + bias1[col], 0.f);
                } else {
                    v += bias1[col] + bias2[col]
                       + WihFull[(size_t)col * 532 + 512 + p0]
                       + WihFull[(size_t)col * 532 + 522 + p1];
                }
                C[(size_t)row * N + col] = v;
            }
        }
    }
}

__global__ void __launch_bounds__(256) fc_kernel(
    const float* __restrict__ Wfc, const float* __restrict__ bfc)
{
    sgemm_body<0, 0>(g_c3, Wfc, g_feat, 512, 3136, 512, bfc, nullptr, nullptr, nullptr);
}

__global__ void __launch_bounds__(256) xw_kernel(
    const float* __restrict__ Wih, const float* __restrict__ bih,
    const float* __restrict__ bhh, const int* __restrict__ pos)
{
    sgemm_body<1, 1>(g_feat, Wih, g_xw, 512, 512, 532, bih, bhh, Wih, pos);
}

// ---------------- persistent LSTM: 32 blocks x 128 threads --------------
__device__ __forceinline__ float sigmoidf_(float x) {
    return 1.0f / (1.0f + __expf(-x));
}

__global__ void __launch_bounds__(128) lstm_kernel(
    const int* __restrict__ done, const float* __restrict__ h0,
    const float* __restrict__ c0, const float* __restrict__ Whh,
    float* __restrict__ out)
{
    int k = blockIdx.x;          // owns hidden units 4k..4k+3
    int t = threadIdx.x;
    int lane = t & 31, w = t >> 5;   // w = gate index in matvec phase

    __shared__ float whh_s[16][HID];     // 16 gate-rows of Whh for this block
    __shared__ float h_sh[HID][BBATCH];  // transposed h
    __shared__ float c_s[4][BBATCH];
    __shared__ float gate_s[4][4][BBATCH]; // [gate][unit][b]
    __shared__ float m_s[BBATCH];

    // load Whh slice: local row r = g*4+ul -> global row g*128 + 4k+ul
    for (int idx = t; idx < 16 * HID; idx += 128) {
        int r = idx >> 7, j = idx & 127;
        int G = (r >> 2) * HID + k * 4 + (r & 3);
        whh_s[r][j] = Whh[(size_t)G * HID + j];
    }
    c_s[w][lane] = c0[lane * HID + k * 4 + w];
    __stcg(&g_hT[0][(k * 4 + w) * BBATCH + lane], h0[lane * HID + k * 4 + w]);
    __threadfence();
    __syncthreads();
    unsigned target = 32;
    if (t == 0) {
        atomicAdd(&g_bar, 1u);
        while (*((volatile unsigned*)&g_bar) < target) {}
    }
    __syncthreads();

    float h_last = 0.f;
    for (int step = 0; step < TSTEPS; step++) {
        int p = step & 1;
        if (t < 32) m_s[t] = 1.0f - (float)done[step * BBATCH + t];
        __syncthreads();
        for (int idx = t; idx < HID * BBATCH; idx += 128) {
            h_sh[idx >> 5][idx & 31] = __ldcg(&g_hT[p][idx]) * m_s[idx & 31];
        }
        __syncthreads();

        // gates: thread (gate=w, batch=lane) accumulates 4 units
        float acc[4];
        const float* xwr = g_xw + (size_t)(step * BBATCH + lane) * 512 + w * HID + k * 4;
#pragma unroll
        for (int ul = 0; ul < 4; ul++) acc[ul] = xwr[ul];
#pragma unroll 4
        for (int j = 0; j < HID; j++) {
            float hv = h_sh[j][lane];
#pragma unroll
            for (int ul = 0; ul < 4; ul++) acc[ul] += hv * whh_s[w * 4 + ul][j];
        }
#pragma unroll
        for (int ul = 0; ul < 4; ul++) gate_s[w][ul][lane] = acc[ul];
        __syncthreads();

        // update: thread (unit=w, batch=lane)
        float iv = sigmoidf_(gate_s[0][w][lane]);
        float fv = sigmoidf_(gate_s[1][w][lane]);
        float gv = tanhf(gate_s[2][w][lane]);
        float ov = sigmoidf_(gate_s[3][w][lane]);
        float cc = fv * (c_s[w][lane] * m_s[lane]) + iv * gv;
        c_s[w][lane] = cc;
        float hh = ov * tanhf(cc);
        h_last = hh;
        __stcg(&g_hT[1 - p][(k * 4 + w) * BBATCH + lane], hh);
        g_hs[(size_t)(step * BBATCH + lane) * HID + k * 4 + w] = hh;
        __threadfence();
        __syncthreads();
        target += 32;
        if (t == 0) {
            atomicAdd(&g_bar, 1u);
            while (*((volatile unsigned*)&g_bar) < target) {}
        }
        __syncthreads();
    }
    // final h, c -> out (B,1,128) regions
    out[12288 + lane * HID + k * 4 + w] = h_last;
    out[16384 + lane * HID + k * 4 + w] = c_s[w][lane];
}

// ---------------- heads: logits (2048x5) + value (2048x1) ---------------
__global__ void heads_kernel(
    const float* __restrict__ Wp, const float* __restrict__ bp,
    const float* __restrict__ Wv, const float* __restrict__ bv,
    float* __restrict__ out)
{
    int row = blockIdx.x * 8 + threadIdx.y;
    int lane = threadIdx.x;
    const float* h = g_hs + (size_t)row * HID;
    float4 hv = *(const float4*)&h[lane * 4];
    float vals[4] = {hv.x, hv.y, hv.z, hv.w};
    float r[6];
#pragma unroll
    for (int a = 0; a < 5; a++) {
        float s = 0.f;
#pragma unroll
        for (int q = 0; q < 4; q++) s += vals[q] * __ldg(&Wp[(lane * 4 + q) * 5 + a]);
        r[a] = s;
    }
    {
        float s = 0.f;
#pragma unroll
        for (int q = 0; q < 4; q++) s += vals[q] * __ldg(&Wv[lane * 4 + q]);
        r[5] = s;
    }
#pragma unroll
    for (int a = 0; a < 6; a++)
#pragma unroll
        for (int off = 16; off > 0; off >>= 1)
            r[a] += __shfl_xor_sync(0xffffffffu, r[a], off);
    if (lane == 0) {
#pragma unroll
        for (int a = 0; a < 5; a++) out[(size_t)row * 5 + a] = r[a] + __ldg(&bp[a]);
        out[10240 + row] = r[5] + __ldg(&bv[0]);
    }
}

// ---------------- launch ----------------
extern "C" void kernel_launch(void* const* d_in, const int* in_sizes, int n_in,
                              void* d_out, int out_size)
{
    const float* image    = (const float*)d_in[0];
    const int*   position = (const int*)d_in[1];
    const int*   done     = (const int*)d_in[2];
    const float* h0       = (const float*)d_in[3];
    const float* c0       = (const float*)d_in[4];
    const float* W1  = (const float*)d_in[5];
    const float* b1  = (const float*)d_in[6];
    const float* W2  = (const float*)d_in[7];
    const float* b2  = (const float*)d_in[8];
    const float* W3  = (const float*)d_in[9];
    const float* b3  = (const float*)d_in[10];
    const float* Wfc = (const float*)d_in[11];
    const float* bfc = (const float*)d_in[12];
    const float* Wih = (const float*)d_in[13];
    const float* Whh = (const float*)d_in[14];
    const float* bih = (const float*)d_in[15];
    const float* bhh = (const float*)d_in[16];
    const float* Wp  = (const float*)d_in[17];
    const float* bp  = (const float*)d_in[18];
    const float* Wv  = (const float*)d_in[19];
    const float* bv  = (const float*)d_in[20];
    float* out = (float*)d_out;

    init_kernel<<<1, 32>>>();
    conv1g_kernel<<<819200 / 256, 256>>>(image, W1, b1);
    conv2g_kernel<<<165888 / 128, 256>>>(W2, b2);
    conv3g_kernel<<<100352 / 128, 256>>>(W3, b3);
    fc_kernel<<<dim3(8, 32), 256>>>(Wfc, bfc);
    xw_kernel<<<dim3(8, 32), 256>>>(Wih, bih, bhh, position);
    lstm_kernel<<<32, 128>>>(done, h0, c0, Whh, out);
    heads_kernel<<<256, dim3(32, 8)>>>(Wp, bp, Wv, bv, out);
}